// round 14
// baseline (speedup 1.0000x reference)
#include <cuda_runtime.h>
#include <math.h>

#define NPTS 16384
#define NCELL 24
#define NCELL3 13824
#define INV_CELL 0.1875f            // NCELL / 128
#define CELLSZ 5.3333333f           // 128 / NCELL
#define CAP 6                       // slots per cell
#define OVF_CAP 256
#define NBRICK 216                  // (24/4)^3 bricks per set
#define NBCELL 216                  // 6^3 staged cells per brick
#define QBLK 128
#define NQBLK (2 * NBRICK + 2)      // 434 blocks

__device__ int    g_ccnt[2][NCELL3];          // raw counts (may exceed CAP)
__device__ float4 g_slots[2][NCELL3 * CAP];   // w = -0.5*||p||^2
__device__ int    g_ovfn[2];
__device__ float4 g_ovf[2][OVF_CAP];
__device__ float  g_acc;
__device__ int    g_done;

// ---- build: bin points into fixed-capacity cells ----
__global__ void build_kernel(const float* __restrict__ A,
                             const float* __restrict__ B) {
    int i = blockIdx.x * blockDim.x + threadIdx.x;   // 0 .. 2*NPTS-1
    int set = i >> 14;
    int idx = i & (NPTS - 1);
    const float* __restrict__ P = set ? B : A;
    float x = P[3 * idx], y = P[3 * idx + 1], z = P[3 * idx + 2];
    int cx = min((int)(x * INV_CELL), NCELL - 1);
    int cy = min((int)(y * INV_CELL), NCELL - 1);
    int cz = min((int)(z * INV_CELL), NCELL - 1);
    int c = (cx * NCELL + cy) * NCELL + cz;
    float4 pt = make_float4(x, y, z, -0.5f * (x * x + y * y + z * z));
    int pos = atomicAdd(&g_ccnt[set][c], 1);
    if (pos < CAP) {
        g_slots[set][c * CAP + pos] = pt;
    } else {
        int o = atomicAdd(&g_ovfn[set], 1);
        if (o < OVF_CAP) g_ovf[set][o] = pt;
    }
}

// ---- rare-path helpers (global memory, per-thread dynamic) ----
__device__ float scan_box(float4 q, int qx, int qy, int qz, int r,
                          const int* __restrict__ ccnt,
                          const float4* __restrict__ slots, float best) {
    int x0 = max(qx - r, 0), x1 = min(qx + r, NCELL - 1);
    int y0 = max(qy - r, 0), y1 = min(qy + r, NCELL - 1);
    int z0 = max(qz - r, 0), z1 = min(qz + r, NCELL - 1);
    for (int ix = x0; ix <= x1; ix++)
        for (int iy = y0; iy <= y1; iy++)
            for (int iz = z0; iz <= z1; iz++) {
                int c = (ix * NCELL + iy) * NCELL + iz;
                int n = min(ccnt[c], CAP);
                const float4* s = slots + c * CAP;
                for (int jj = 0; jj < n; jj++) {
                    float4 t = s[jj];
                    float e = fmaf(q.x, t.x, fmaf(q.y, t.y, fmaf(q.z, t.z, t.w)));
                    best = fmaxf(best, e);
                }
            }
    return best;
}

__device__ float nn_finish(float4 q, int qx, int qy, int qz, int rs,
                           float best, int startr) {
    const int* __restrict__ ccnt = g_ccnt[rs];
    const float4* __restrict__ slots = g_slots[rs];
    float d2 = -2.0f * (q.w + best);
    for (int r = startr; r <= NCELL; r++) {
        float rb = (r - 1) * CELLSZ;
        if (d2 <= rb * rb) break;       // all unscanned points strictly farther
        best = scan_box(q, qx, qy, qz, r, ccnt, slots, best);
        d2 = -2.0f * (q.w + best);
    }
    return d2;
}

// ---- query: block per 4x4x4 brick; 6x6x6 ref neighborhood staged in SMEM ----
__global__ __launch_bounds__(QBLK) void query_kernel(float* __restrict__ out) {
    __shared__ float4 s_pts[NBCELL * CAP];   // 20736 B
    __shared__ int    s_cnt[NBCELL];
    __shared__ float  red[QBLK / 32];
    __shared__ int    s_last;
    int bid = blockIdx.x;
    int tid = threadIdx.x;
    float v = 0.0f;

    if (bid < 2 * NBRICK) {
        int set = (bid >= NBRICK);
        int bk = bid - set * NBRICK;
        int rs = set ^ 1;
        int bx = bk / 36, by = (bk / 6) % 6, bz = bk % 6;

        // stage counts of the 6^3 neighborhood (OOB cells -> 0)
        for (int i = tid; i < NBCELL; i += QBLK) {
            int lx = i / 36, ly = (i / 6) % 6, lz = i % 6;
            int gx = bx * 4 - 1 + lx, gy = by * 4 - 1 + ly, gz = bz * 4 - 1 + lz;
            int n = 0;
            if ((unsigned)gx < NCELL && (unsigned)gy < NCELL && (unsigned)gz < NCELL)
                n = min(g_ccnt[rs][(gx * NCELL + gy) * NCELL + gz], CAP);
            s_cnt[i] = n;
        }
        __syncthreads();

        // stage points (only occupied slots; coalesced across consecutive i)
        for (int i = tid; i < NBCELL * CAP; i += QBLK) {
            int li = i / CAP, sl = i - li * CAP;
            if (sl < s_cnt[li]) {
                int lx = li / 36, ly = (li / 6) % 6, lz = li % 6;
                int gx = bx * 4 - 1 + lx, gy = by * 4 - 1 + ly, gz = bz * 4 - 1 + lz;
                int c = (gx * NCELL + gy) * NCELL + gz;
                s_pts[i] = g_slots[rs][c * CAP + sl];
            }
        }
        __syncthreads();

        // thread = (interior cell, slot parity)
        int ic = tid & 63;
        int jb = tid >> 6;                      // 0 or 1
        int icx = ic >> 4, icy = (ic >> 2) & 3, icz = ic & 3;
        int gqx = bx * 4 + icx, gqy = by * 4 + icy, gqz = bz * 4 + icz;
        int gq = (gqx * NCELL + gqy) * NCELL + gqz;
        int qcnt = min(g_ccnt[set][gq], CAP);
        int novf = min(g_ovfn[rs], OVF_CAP);

        for (int j = jb; j < qcnt; j += 2) {
            float4 q = g_slots[set][gq * CAP + j];
            float best = -1e30f;

            #pragma unroll
            for (int dx = -1; dx <= 1; dx++) {
                #pragma unroll
                for (int dy = -1; dy <= 1; dy++) {
                    #pragma unroll
                    for (int dz = -1; dz <= 1; dz++) {
                        int li = ((icx + 1 + dx) * 6 + (icy + 1 + dy)) * 6
                                 + (icz + 1 + dz);
                        int n = s_cnt[li];
                        const float4* s = &s_pts[li * CAP];
                        #pragma unroll
                        for (int jj = 0; jj < 2; jj++) {     // covers ~88% of pts
                            float4 p = s[jj];
                            float e = fmaf(q.x, p.x,
                                      fmaf(q.y, p.y, fmaf(q.z, p.z, p.w)));
                            best = (jj < n) ? fmaxf(best, e) : best;
                        }
                        if (n > 2) {                          // rare tail
                            for (int jj = 2; jj < n; jj++) {
                                float4 p = s[jj];
                                float e = fmaf(q.x, p.x,
                                          fmaf(q.y, p.y, fmaf(q.z, p.z, p.w)));
                                best = fmaxf(best, e);
                            }
                        }
                    }
                }
            }

            // overflow refs (expected ~0-4, warp-uniform count)
            for (int o = 0; o < novf; o++) {
                float4 p = g_ovf[rs][o];
                float e = fmaf(q.x, p.x, fmaf(q.y, p.y, fmaf(q.z, p.z, p.w)));
                best = fmaxf(best, e);
            }

            float d2 = -2.0f * (q.w + best);
            if (d2 > CELLSZ * CELLSZ)             // ~0.7%: expand via global
                d2 = nn_finish(q, gqx, gqy, gqz, rs, best, 2);
            v += sqrtf(fmaxf(d2, 0.0f));
        }
    } else {
        // overflow points as queries (expected empty)
        int set = bid - 2 * NBRICK;
        int rs = set ^ 1;
        int no = min(g_ovfn[set], OVF_CAP);
        if (tid < no) {
            float4 q = g_ovf[set][tid];
            int qx = min((int)(q.x * INV_CELL), NCELL - 1);
            int qy = min((int)(q.y * INV_CELL), NCELL - 1);
            int qz = min((int)(q.z * INV_CELL), NCELL - 1);
            float best = scan_box(q, qx, qy, qz, 1, g_ccnt[rs], g_slots[rs],
                                  -1e30f);
            int novf = min(g_ovfn[rs], OVF_CAP);
            for (int o = 0; o < novf; o++) {
                float4 p = g_ovf[rs][o];
                float e = fmaf(q.x, p.x, fmaf(q.y, p.y, fmaf(q.z, p.z, p.w)));
                best = fmaxf(best, e);
            }
            float d2 = nn_finish(q, qx, qy, qz, rs, best, 2);
            v = sqrtf(fmaxf(d2, 0.0f));
        }
    }

    // ---- block sum -> global atomic; last block writes out + resets ----
    #pragma unroll
    for (int o = 16; o > 0; o >>= 1) v += __shfl_down_sync(0xFFFFFFFFu, v, o);
    int lane = tid & 31, wid = tid >> 5;
    if (lane == 0) red[wid] = v;
    __syncthreads();
    if (tid == 0) {
        float bs = 0.0f;
        #pragma unroll
        for (int w = 0; w < QBLK / 32; w++) bs += red[w];
        atomicAdd(&g_acc, bs);
        __threadfence();
        s_last = (atomicAdd(&g_done, 1) == NQBLK - 1);
    }
    __syncthreads();
    if (s_last) {
        if (tid == 0) {
            out[0] = *((volatile float*)&g_acc) * (1.0f / (2.0f * NPTS));
            g_acc = 0.0f;
            g_done = 0;
            g_ovfn[0] = 0;
            g_ovfn[1] = 0;
        }
        for (int c = tid; c < 2 * NCELL3; c += QBLK)
            ((int*)g_ccnt)[c] = 0;
    }
}

extern "C" void kernel_launch(void* const* d_in, const int* in_sizes, int n_in,
                              void* d_out, int out_size) {
    const float* a = (const float*)d_in[0];
    const float* b = (const float*)d_in[1];
    float* out = (float*)d_out;

    build_kernel<<<(2 * NPTS) / 256, 256>>>(a, b);
    query_kernel<<<NQBLK, QBLK>>>(out);
}

// round 15
// speedup vs baseline: 1.9623x; 1.9623x over previous
#include <cuda_runtime.h>
#include <math.h>

#define NPTS 16384
#define NCELL 24
#define NCELL3 13824
#define INV_CELL 0.1875f            // NCELL / 128
#define CELLSZ 5.3333333f           // 128 / NCELL
#define SCAN_T 1024
#define CHUNK 14                    // ceil(13824 / 1024)
#define QBLK 128
#define NQBLK ((2 * NPTS) / QBLK)   // 256 query blocks

__device__ int g_cnt[2][NCELL3];
__device__ int g_start[2][NCELL3 + 1];
__device__ int g_cursor[2][NCELL3];
__device__ float4 g_pts[2][NPTS];   // cell-sorted; w = -0.5*||p||^2
__device__ float g_acc;
__device__ int g_done;

__device__ __forceinline__ int cell_of(float x, float y, float z) {
    int cx = min((int)(x * INV_CELL), NCELL - 1);
    int cy = min((int)(y * INV_CELL), NCELL - 1);
    int cz = min((int)(z * INV_CELL), NCELL - 1);
    return (cx * NCELL + cy) * NCELL + cz;
}

__global__ void count_kernel(const float* __restrict__ A,
                             const float* __restrict__ B) {
    int i = blockIdx.x * blockDim.x + threadIdx.x;   // 0 .. 2*NPTS-1
    int set = i >> 14;
    int idx = i & (NPTS - 1);
    const float* __restrict__ P = set ? B : A;
    float x = P[3 * idx], y = P[3 * idx + 1], z = P[3 * idx + 2];
    atomicAdd(&g_cnt[set][cell_of(x, y, z)], 1);
}

// 2 blocks (one per set): exclusive scan of 13824 counts; re-zero g_cnt after use.
__global__ void scan_kernel() {
    __shared__ int sh[SCAN_T];
    int set = blockIdx.x;
    int t = threadIdx.x;
    int base = t * CHUNK;

    int loc[CHUNK];
    int sum = 0;
    #pragma unroll
    for (int u = 0; u < CHUNK; u++) {
        int c = base + u;
        loc[u] = (c < NCELL3) ? g_cnt[set][c] : 0;
        sum += loc[u];
    }
    sh[t] = sum;
    __syncthreads();
    for (int off = 1; off < SCAN_T; off <<= 1) {
        int v = sh[t];
        int w = (t >= off) ? sh[t - off] : 0;
        __syncthreads();
        sh[t] = v + w;
        __syncthreads();
    }
    int excl = (t == 0) ? 0 : sh[t - 1];
    #pragma unroll
    for (int u = 0; u < CHUNK; u++) {
        int c = base + u;
        if (c < NCELL3) {
            g_start[set][c] = excl;
            g_cursor[set][c] = excl;
            g_cnt[set][c] = 0;          // ready for next graph replay
            excl += loc[u];
        }
    }
    if (t == SCAN_T - 1) g_start[set][NCELL3] = excl;   // = NPTS
}

__global__ void scatter_kernel(const float* __restrict__ A,
                               const float* __restrict__ B) {
    int i = blockIdx.x * blockDim.x + threadIdx.x;
    int set = i >> 14;
    int idx = i & (NPTS - 1);
    const float* __restrict__ P = set ? B : A;
    float x = P[3 * idx], y = P[3 * idx + 1], z = P[3 * idx + 2];
    int c = cell_of(x, y, z);
    int pos = atomicAdd(&g_cursor[set][c], 1);
    g_pts[set][pos] = make_float4(x, y, z, -0.5f * (x * x + y * y + z * z));
}

// One thread per cell-sorted query (R6-proven simple dynamic loop);
// fused final reduction + output + state reset.
__global__ __launch_bounds__(QBLK) void query_kernel(float* __restrict__ out) {
    __shared__ float red[QBLK / 32];
    __shared__ int s_last;
    int i = blockIdx.x * QBLK + threadIdx.x;   // 0 .. 2*NPTS-1
    int qs = i >> 14;
    int rs = qs ^ 1;
    int idx = i & (NPTS - 1);

    float4 q = g_pts[qs][idx];
    int qx = min((int)(q.x * INV_CELL), NCELL - 1);
    int qy = min((int)(q.y * INV_CELL), NCELL - 1);
    int qz = min((int)(q.z * INV_CELL), NCELL - 1);

    const int* __restrict__ start = g_start[rs];
    const float4* __restrict__ pts = g_pts[rs];

    float best = -1e30f;   // max over refs of e = q.r - 0.5*||r||^2
    for (int r = 1; r <= NCELL; r++) {
        int x0 = max(qx - r, 0), x1 = min(qx + r, NCELL - 1);
        int y0 = max(qy - r, 0), y1 = min(qy + r, NCELL - 1);
        int z0 = max(qz - r, 0), z1 = min(qz + r, NCELL - 1);
        for (int ix = x0; ix <= x1; ix++) {
            for (int iy = y0; iy <= y1; iy++) {
                int base = (ix * NCELL + iy) * NCELL;
                int p0 = start[base + z0];
                int p1 = start[base + z1 + 1];   // contiguous z-span
                for (int p = p0; p < p1; p++) {
                    float4 t = pts[p];
                    float e = fmaf(q.x, t.x, fmaf(q.y, t.y, fmaf(q.z, t.z, t.w)));
                    best = fmaxf(best, e);
                }
            }
        }
        float d2c = -2.0f * (q.w + best);
        float rb = r * CELLSZ;
        if (d2c <= rb * rb) break;   // all unscanned points strictly farther
    }

    float d2 = -2.0f * (q.w + best);
    float v = sqrtf(fmaxf(d2, 0.0f));

    // ---- block sum -> global atomic; last block writes out + resets ----
    #pragma unroll
    for (int o = 16; o > 0; o >>= 1) v += __shfl_down_sync(0xFFFFFFFFu, v, o);
    int lane = threadIdx.x & 31, wid = threadIdx.x >> 5;
    if (lane == 0) red[wid] = v;
    __syncthreads();
    if (threadIdx.x == 0) {
        float bs = 0.0f;
        #pragma unroll
        for (int w = 0; w < QBLK / 32; w++) bs += red[w];
        atomicAdd(&g_acc, bs);
        __threadfence();
        s_last = (atomicAdd(&g_done, 1) == NQBLK - 1);
    }
    __syncthreads();
    if (s_last && threadIdx.x == 0) {
        out[0] = *((volatile float*)&g_acc) * (1.0f / (2.0f * NPTS));
        g_acc = 0.0f;                 // reset for next graph replay
        g_done = 0;
    }
}

extern "C" void kernel_launch(void* const* d_in, const int* in_sizes, int n_in,
                              void* d_out, int out_size) {
    const float* a = (const float*)d_in[0];
    const float* b = (const float*)d_in[1];
    float* out = (float*)d_out;

    count_kernel<<<(2 * NPTS) / 256, 256>>>(a, b);
    scan_kernel<<<2, SCAN_T>>>();
    scatter_kernel<<<(2 * NPTS) / 256, 256>>>(a, b);
    query_kernel<<<NQBLK, QBLK>>>(out);
}